// round 6
// baseline (speedup 1.0000x reference)
#include <cuda_runtime.h>
#include <math.h>

#define BB 64
#define SS 1024
#define II 512
#define HH 1024
#define OO 256
#define BH (BB * HH)

// persistent-kernel grid: 32 col-groups x 4 batch-groups
#define GC 32
#define GB 4
#define NBLK (GC * GB)
#define COLS_PB 32
#define ROWS_PB 16
#define KF 16
#define KI 64

// padded smem strides (floats)
#define WS 36
#define HS 17
#define RKG 584
#define RROW 36

#define SMEM_WH_FLOATS (1024 * WS)
#define SMEM_H_FLOATS  (1024 * HS)
#define SMEM_TOTAL_B   ((SMEM_WH_FLOATS + SMEM_H_FLOATS) * 4)

typedef unsigned long long ull;

// packed fp32x2 FMA (sm_103a FFMA2 — only reachable via PTX)
#define FFMA2(acc, a, b) \
    asm("fma.rn.f32x2 %0, %1, %2, %0;" : "+l"(acc) : "l"(a), "l"(b))
// broadcast-pack a scalar float into both halves of a b64
#define BPACK2(dst, s) \
    asm("mov.b64 %0, {%1, %1};" : "=l"(dst) : "f"(s))
#define UNPACK2(lo, hi, in) \
    asm("mov.b64 {%0, %1}, %2;" : "=f"(lo), "=f"(hi) : "l"(in))

__device__ unsigned int g_bar;

__global__ void init_kernel() { g_bar = 0u; }

// ---------------------------------------------------------------------------
// Kernel 1: x_proj.  out_all[s*B*H + b*H + j] = dot(x[b,s,:], Wx[j,:]) + bias[j]
// M=64 (batch) x N=64 (hidden), K=512, BK=16.  FFMA2 core: 8 packed FMA per k.
// ---------------------------------------------------------------------------
__global__ __launch_bounds__(256) void xproj_kernel(
    const float* __restrict__ x, const float* __restrict__ Wx,
    const float* __restrict__ bias, float* __restrict__ out)
{
    __shared__ __align__(16) float As[16][68];  // [k][b]
    __shared__ __align__(16) float Bs[16][68];  // [k][j]

    const int s  = blockIdx.y;
    const int n0 = blockIdx.x * 64;
    const int t  = threadIdx.x;
    const int tx = t & 15;
    const int ty = t >> 4;
    const int lb = t >> 2;
    const int lk = (t & 3) << 2;

    ull acc2[4][2];  // [a-row][col pair]  (pair = 2 adjacent j)
#pragma unroll
    for (int r = 0; r < 4; r++) { acc2[r][0] = 0ULL; acc2[r][1] = 0ULL; }

    const float* xrow = x  + ((size_t)lb * SS + s) * II;
    const float* wrow = Wx + (size_t)(n0 + lb) * II;

    for (int kc = 0; kc < II; kc += 16) {
        float4 va = *(const float4*)(xrow + kc + lk);
        float4 vb = *(const float4*)(wrow + kc + lk);
        __syncthreads();
        As[lk + 0][lb] = va.x; As[lk + 1][lb] = va.y;
        As[lk + 2][lb] = va.z; As[lk + 3][lb] = va.w;
        Bs[lk + 0][lb] = vb.x; Bs[lk + 1][lb] = vb.y;
        Bs[lk + 2][lb] = vb.z; Bs[lk + 3][lb] = vb.w;
        __syncthreads();
#pragma unroll
        for (int k = 0; k < 16; k++) {
            float4 a = *(const float4*)&As[k][ty << 2];
            ulonglong2 w2 = *(const ulonglong2*)&Bs[k][tx << 2];
            ull pa0, pa1, pa2, pa3;
            BPACK2(pa0, a.x); BPACK2(pa1, a.y);
            BPACK2(pa2, a.z); BPACK2(pa3, a.w);
            FFMA2(acc2[0][0], pa0, w2.x); FFMA2(acc2[0][1], pa0, w2.y);
            FFMA2(acc2[1][0], pa1, w2.x); FFMA2(acc2[1][1], pa1, w2.y);
            FFMA2(acc2[2][0], pa2, w2.x); FFMA2(acc2[2][1], pa2, w2.y);
            FFMA2(acc2[3][0], pa3, w2.x); FFMA2(acc2[3][1], pa3, w2.y);
        }
    }

    const int jbase = n0 + (tx << 2);
    float4 bv = *(const float4*)&bias[jbase];
#pragma unroll
    for (int r = 0; r < 4; r++) {
        const int b = (ty << 2) + r;
        float c0, c1, c2, c3;
        UNPACK2(c0, c1, acc2[r][0]);
        UNPACK2(c2, c3, acc2[r][1]);
        float4 o;
        o.x = c0 + bv.x; o.y = c1 + bv.y;
        o.z = c2 + bv.z; o.w = c3 + bv.w;
        *(float4*)&out[(size_t)s * BH + (size_t)b * HH + jbase] = o;
    }
}

// ---------------------------------------------------------------------------
// Kernel 2: persistent recurrence with FFMA2 core.
//   xp[b][j] <- tanh( xp[b][j] + sum_k hprev[b][k] * Wh[j][k] )   in place
// 128 co-resident blocks, grid barrier per step.  Wh slice smem-resident.
// Thread tile 4 rows x 8 cols (4 col-pairs), 16-way K-split, stride-16
// k interleave.  16 FFMA2 + 4 packs + 6 LDS per iteration.
// ---------------------------------------------------------------------------
__global__ __launch_bounds__(256, 1) void rnn_persistent(
    const float* __restrict__ Wh, float* __restrict__ all)
{
    extern __shared__ float smem[];
    float* whs = smem;                       // [1024][WS]
    float* h_s = smem + SMEM_WH_FLOATS;      // [1024][HS]; reused as red[]

    const int t   = threadIdx.x;
    const int bid = blockIdx.x;
    const int j0  = (bid & (GC - 1)) * COLS_PB;
    const int rb0 = (bid >> 5) * ROWS_PB;

    const int cg = t & 3;           // col group: cols cg*8 .. +7
    const int r4 = (t >> 2) & 3;    // row group: rows r4*4 .. +3
    const int kg = t >> 4;          // k group 0..15, k = kg + 16*i

    // ---- load resident Wh slice, transposed to [k][col] with pad WS ----
    for (int idx = t; idx < COLS_PB * 256; idx += 256) {
        const int c  = idx >> 8;
        const int kq = idx & 255;
        float4 v = *(const float4*)(Wh + (size_t)(j0 + c) * HH + (kq << 2));
        const int kb = (kq << 2) * WS + c;
        whs[kb]          = v.x;
        whs[kb + WS]     = v.y;
        whs[kb + 2 * WS] = v.z;
        whs[kb + 3 * WS] = v.w;
    }

    for (int s = 0; s < SS; s++) {
        float* cur = all + (size_t)s * BH;

        if (s > 0) {
            const float* hprev = all + (size_t)(s - 1) * BH;

            // ---- fill h tile [16 rows][1024 k] -> h_s[k][row], pad HS ----
            __syncthreads();
#pragma unroll 4
            for (int idx = t; idx < ROWS_PB * 256; idx += 256) {
                const int r  = idx >> 8;
                const int kq = idx & 255;
                float4 v = *(const float4*)(hprev + (size_t)(rb0 + r) * HH + (kq << 2));
                const int hb = (kq << 2) * HS + r;
                h_s[hb]          = v.x;
                h_s[hb + HS]     = v.y;
                h_s[hb + 2 * HS] = v.z;
                h_s[hb + 3 * HS] = v.w;
            }
            __syncthreads();

            // ---- main loop ----
            ull acc2[4][4];  // [row][col pair]
#pragma unroll
            for (int r = 0; r < 4; r++)
#pragma unroll
                for (int c = 0; c < 4; c++) acc2[r][c] = 0ULL;

            int hb = kg * HS + (r4 << 2);
            int wb = kg * WS + (cg << 3);
#pragma unroll 4
            for (int i = 0; i < KI; i++) {
                const float h0 = h_s[hb + 0];
                const float h1 = h_s[hb + 1];
                const float h2 = h_s[hb + 2];
                const float h3 = h_s[hb + 3];
                ulonglong2 wa = *(const ulonglong2*)&whs[wb];
                ulonglong2 wc = *(const ulonglong2*)&whs[wb + 4];
                ull hp0, hp1, hp2, hp3;
                BPACK2(hp0, h0); BPACK2(hp1, h1);
                BPACK2(hp2, h2); BPACK2(hp3, h3);
                FFMA2(acc2[0][0], hp0, wa.x); FFMA2(acc2[0][1], hp0, wa.y);
                FFMA2(acc2[0][2], hp0, wc.x); FFMA2(acc2[0][3], hp0, wc.y);
                FFMA2(acc2[1][0], hp1, wa.x); FFMA2(acc2[1][1], hp1, wa.y);
                FFMA2(acc2[1][2], hp1, wc.x); FFMA2(acc2[1][3], hp1, wc.y);
                FFMA2(acc2[2][0], hp2, wa.x); FFMA2(acc2[2][1], hp2, wa.y);
                FFMA2(acc2[2][2], hp2, wc.x); FFMA2(acc2[2][3], hp2, wc.y);
                FFMA2(acc2[3][0], hp3, wa.x); FFMA2(acc2[3][1], hp3, wa.y);
                FFMA2(acc2[3][2], hp3, wc.x); FFMA2(acc2[3][3], hp3, wc.y);
                hb += 16 * HS;
                wb += 16 * WS;
            }

            // ---- K-split reduction via smem (aliases h_s) ----
            __syncthreads();
            float* red = h_s;
#pragma unroll
            for (int ri = 0; ri < 4; ri++) {
                const int row = (r4 << 2) + ri;
                const int rb = kg * RKG + row * RROW + (cg << 3);
                ulonglong2 pa, pb;
                pa.x = acc2[ri][0]; pa.y = acc2[ri][1];
                pb.x = acc2[ri][2]; pb.y = acc2[ri][3];
                *(ulonglong2*)&red[rb]     = pa;   // bits = 4 consecutive floats
                *(ulonglong2*)&red[rb + 4] = pb;
            }
            __syncthreads();

            // ---- epilogue ----
#pragma unroll
            for (int oi = 0; oi < 2; oi++) {
                const int o   = t + (oi << 8);
                const int row = o >> 5;
                const int col = o & 31;
                float sum = 0.0f;
#pragma unroll
                for (int kk = 0; kk < KF; kk++)
                    sum += red[kk * RKG + row * RROW + col];
                float* p = cur + (size_t)(rb0 + row) * HH + j0 + col;
                *p = tanhf(*p + sum);
            }
        } else {
#pragma unroll
            for (int oi = 0; oi < 2; oi++) {
                const int o   = t + (oi << 8);
                const int row = o >> 5;
                const int col = o & 31;
                float* p = cur + (size_t)(rb0 + row) * HH + j0 + col;
                *p = tanhf(*p);
            }
        }

        // ---- grid-wide barrier ----
        __threadfence();
        __syncthreads();
        if (t == 0) {
            atomicAdd(&g_bar, 1u);
            const unsigned target = (unsigned)(s + 1) * (unsigned)NBLK;
            while (*((volatile unsigned*)&g_bar) < target) { }
        }
        __syncthreads();
    }
}

// ---------------------------------------------------------------------------
// Kernel 3: readout.  y[b][o] = dot(h_last[b,:], Wout[o,:]) + bout[o]
// Grid (B, 8): block = one batch row x 32 outputs.  512 blocks keep SMs busy.
// ---------------------------------------------------------------------------
__global__ __launch_bounds__(256) void readout_kernel(
    const float* __restrict__ hlast, const float* __restrict__ Wout,
    const float* __restrict__ bout, float* __restrict__ y)
{
    __shared__ float hs[HH];
    const int b  = blockIdx.x;
    const int o0 = blockIdx.y * 32;
    for (int i = threadIdx.x; i < HH; i += 256)
        hs[i] = hlast[(size_t)b * HH + i];
    __syncthreads();

    const int warp = threadIdx.x >> 5;
    const int lane = threadIdx.x & 31;
#pragma unroll
    for (int oi = 0; oi < 4; oi++) {
        const int o = o0 + warp * 4 + oi;
        const float* wr = Wout + (size_t)o * HH;
        float a = 0.0f;
#pragma unroll 8
        for (int k = lane; k < HH; k += 32) a += hs[k] * wr[k];
#pragma unroll
        for (int off = 16; off; off >>= 1)
            a += __shfl_down_sync(0xffffffffu, a, off);
        if (lane == 0) y[(size_t)b * OO + o] = a + bout[o];
    }
}

// ---------------------------------------------------------------------------
extern "C" void kernel_launch(void* const* d_in, const int* in_sizes, int n_in,
                              void* d_out, int out_size)
{
    const float* x    = (const float*)d_in[0];
    const float* Wx   = (const float*)d_in[1];
    const float* Wh   = (const float*)d_in[2];
    const float* bias = (const float*)d_in[3];
    const float* Wout = (const float*)d_in[4];
    const float* bout = (const float*)d_in[5];

    float* y   = (float*)d_out;               // [64, 256]
    float* all = (float*)d_out + BB * OO;     // [1024, 64, 1024]

    cudaFuncSetAttribute(rnn_persistent,
                         cudaFuncAttributeMaxDynamicSharedMemorySize,
                         SMEM_TOTAL_B);

    init_kernel<<<1, 1>>>();

    dim3 g1(HH / 64, SS);
    xproj_kernel<<<g1, 256>>>(x, Wx, bias, all);

    rnn_persistent<<<NBLK, 256, SMEM_TOTAL_B>>>(Wh, all);

    dim3 g3(BB, 8);
    readout_kernel<<<g3, 256>>>(all + (size_t)(SS - 1) * BH, Wout, bout, y);
}